// round 10
// baseline (speedup 1.0000x reference)
#include <cuda_runtime.h>

// ---------------------------------------------------------------------------
// Problem constants
// ---------------------------------------------------------------------------
#define D_MODEL 2048
#define NHEADS  16
#define DHEAD   128
#define SEQ     2048
#define BATCH   2
#define MTOT    (BATCH * SEQ)        // 4096 rows
#define OUTSZ   (MTOT * D_MODEL)     // 8388608 elements per output tensor

// Scratch buffers (no cudaMalloc allowed -> device globals)
__device__ float g_q [MTOT * D_MODEL];  // q  (then qn in-place)
__device__ float g_kn[MTOT * D_MODEL];  // normalized k
__device__ float g_z [MTOT * D_MODEL];  // attention output (pre out-proj)

// ---------------------------------------------------------------------------
// Packed fp32x2 helpers (Blackwell FFMA2 path: full-rate fp32)
// ---------------------------------------------------------------------------
typedef unsigned long long u64;

__device__ __forceinline__ u64 f2_pack(float lo, float hi) {
    u64 r; asm("mov.b64 %0, {%1, %2};" : "=l"(r) : "f"(lo), "f"(hi)); return r;
}
__device__ __forceinline__ u64 f2_dup(float x) { return f2_pack(x, x); }
__device__ __forceinline__ void f2_fma(u64& d, u64 a, u64 b) {
    asm("fma.rn.f32x2 %0, %1, %2, %0;" : "+l"(d) : "l"(a), "l"(b));
}
__device__ __forceinline__ u64 f2_mul(u64 a, u64 b) {
    u64 r; asm("mul.rn.f32x2 %0, %1, %2;" : "=l"(r) : "l"(a), "l"(b)); return r;
}
__device__ __forceinline__ void f2_unpack(u64 v, float& lo, float& hi) {
    asm("mov.b64 {%0, %1}, %2;" : "=f"(lo), "=f"(hi) : "l"(v));
}

// ---------------------------------------------------------------------------
// GEMM: C[m,n] = sum_k A[m,k] * B[n,k] + bias[n]     (A:[M,K], B:[N,K] row-major)
// Output routed into up-to-3 segment pointers of width segN each.
// BM=BN=128, BK=16, 256 threads, 8x8 per thread (4+64 split).
// Single-buffered smem, 2 CTAs/SM (cross-CTA latency overlap),
// packed f32x2 accumulators (pairs along n).
// ---------------------------------------------------------------------------
#define BM 128
#define BN 128
#define BK 16

__global__ __launch_bounds__(256, 2)
void gemm_bias_nt(const float* __restrict__ A, const float* __restrict__ B,
                  const float* __restrict__ bias,
                  float* __restrict__ out0, float* __restrict__ out1,
                  float* __restrict__ out2,
                  int M, int N, int K, int segN)
{
    __shared__ __align__(16) float As[BK][BM];
    __shared__ __align__(16) float Bs[BK][BN];

    const int tid = threadIdx.x;
    const int tx  = tid & 15;
    const int ty  = tid >> 4;
    const int m0  = blockIdx.y * BM;
    const int n0  = blockIdx.x * BN;

    const float* Ab = A + (size_t)m0 * K;
    const float* Bb = B + (size_t)n0 * K;

    u64 acc2[8][4];
#pragma unroll
    for (int i = 0; i < 8; i++)
#pragma unroll
        for (int j = 0; j < 4; j++) acc2[i][j] = 0ull;

    const int ntiles = K / BK;
    for (int t = 0; t < ntiles; t++) {
        const int k0 = t * BK;
#pragma unroll
        for (int i = 0; i < 2; i++) {
            int idx = tid + i * 256;
            int row = idx >> 2;
            int kg  = (idx & 3) << 2;
            float4 av = *(const float4*)(Ab + (size_t)row * K + k0 + kg);
            As[kg + 0][row] = av.x; As[kg + 1][row] = av.y;
            As[kg + 2][row] = av.z; As[kg + 3][row] = av.w;
            float4 bv = *(const float4*)(Bb + (size_t)row * K + k0 + kg);
            Bs[kg + 0][row] = bv.x; Bs[kg + 1][row] = bv.y;
            Bs[kg + 2][row] = bv.z; Bs[kg + 3][row] = bv.w;
        }
        __syncthreads();

#pragma unroll
        for (int kk = 0; kk < BK; kk++) {
            float4 a0 = *(const float4*)&As[kk][ty * 4];
            float4 a1 = *(const float4*)&As[kk][ty * 4 + 64];
            float4 b0 = *(const float4*)&Bs[kk][tx * 4];
            float4 b1 = *(const float4*)&Bs[kk][tx * 4 + 64];
            u64 bp[4];
            bp[0] = f2_pack(b0.x, b0.y); bp[1] = f2_pack(b0.z, b0.w);
            bp[2] = f2_pack(b1.x, b1.y); bp[3] = f2_pack(b1.z, b1.w);
            float av[8] = {a0.x, a0.y, a0.z, a0.w, a1.x, a1.y, a1.z, a1.w};
#pragma unroll
            for (int i = 0; i < 8; i++) {
                u64 ad = f2_dup(av[i]);
#pragma unroll
                for (int j = 0; j < 4; j++)
                    f2_fma(acc2[i][j], ad, bp[j]);
            }
        }
        __syncthreads();
    }

    // epilogue: bias + segmented store (each 128-wide block tile lies in one segment)
#pragma unroll
    for (int i = 0; i < 8; i++) {
        const int gm = m0 + ((i < 4) ? (ty * 4 + i) : (64 + ty * 4 + (i - 4)));
#pragma unroll
        for (int jh = 0; jh < 2; jh++) {
            const int gn  = n0 + tx * 4 + jh * 64;
            const int seg = gn / segN;
            float* o = (seg == 0) ? out0 : ((seg == 1) ? out1 : out2);
            float4 v;
            f2_unpack(acc2[i][jh * 2 + 0], v.x, v.y);
            f2_unpack(acc2[i][jh * 2 + 1], v.z, v.w);
            v.x += bias[gn + 0];
            v.y += bias[gn + 1];
            v.z += bias[gn + 2];
            v.w += bias[gn + 3];
            *(float4*)(o + (size_t)gm * segN + (gn - seg * segN)) = v;
        }
    }
}

// ---------------------------------------------------------------------------
// RMSNorm over contiguous 128-float vectors: out = x * rsqrt(mean(x^2)+eps) * w
// one warp per vector
// ---------------------------------------------------------------------------
__global__ __launch_bounds__(256)
void rmsnorm128(const float* __restrict__ in, float* __restrict__ out,
                const float* __restrict__ w)
{
    const int row  = blockIdx.x * 8 + (threadIdx.x >> 5);
    const int lane = threadIdx.x & 31;
    const size_t base = (size_t)row * DHEAD + lane * 4;
    float4 xv = *(const float4*)(in + base);
    float ss = xv.x * xv.x + xv.y * xv.y + xv.z * xv.z + xv.w * xv.w;
#pragma unroll
    for (int msk = 16; msk; msk >>= 1)
        ss += __shfl_xor_sync(0xffffffffu, ss, msk);
    const float r = rsqrtf(ss * (1.0f / 128.0f) + 1e-6f);
    float4 wv = *(const float4*)(w + lane * 4);
    float4 ov;
    ov.x = xv.x * r * wv.x;
    ov.y = xv.y * r * wv.y;
    ov.z = xv.z * r * wv.z;
    ov.w = xv.w * r * wv.w;
    *(float4*)(out + base) = ov;
}

// ---------------------------------------------------------------------------
// Flash attention (non-causal, scale = 1.0), fp32 with f32x2 inner loops.
// Grid: (SEQ/BQ, NHEADS, BATCH). Block: 256 threads (16x16).
// ---------------------------------------------------------------------------
#define BQ    64
#define BKT   64
#define QPAD  132   // Qs row stride (floats)
#define KTPAD 68    // KsT row stride (floats)
#define PPAD  65    // Ps row stride (floats)

#define ATTN_SMEM_FLOATS (BQ * QPAD + DHEAD * KTPAD + BKT * DHEAD + BQ * PPAD)

__global__ __launch_bounds__(256, 1)
void attn_flash(const float* __restrict__ Q, const float* __restrict__ Kn,
                const float* __restrict__ V, float* __restrict__ Z)
{
    extern __shared__ __align__(16) float sm[];
    float* Qs  = sm;                        // [BQ][QPAD]
    float* KsT = Qs  + BQ * QPAD;           // [DHEAD][KTPAD]  (transposed K)
    float* Vs  = KsT + DHEAD * KTPAD;       // [BKT][DHEAD]
    float* Ps  = Vs  + BKT * DHEAD;         // [BQ][PPAD]

    const int tid = threadIdx.x;
    const int tx  = tid & 15;
    const int ty  = tid >> 4;
    const int qt  = blockIdx.x;
    const int h   = blockIdx.y;
    const int b   = blockIdx.z;

    const size_t rowbase = (size_t)b * SEQ;
    const int    hb      = h * DHEAD;
    const int    q0      = qt * BQ;

    // Load Q tile (reused for all K tiles)
    for (int idx = tid; idx < BQ * (DHEAD / 4); idx += 256) {
        int i  = idx >> 5;
        int d4 = (idx & 31) << 2;
        float4 v = *(const float4*)(Q + (rowbase + q0 + i) * D_MODEL + hb + d4);
        *(float4*)(Qs + i * QPAD + d4) = v;
    }

    u64 o2[4][4];   // 4 rows x 8 cols packed in pairs
    float mrow[4], lrow[4];
#pragma unroll
    for (int r = 0; r < 4; r++) {
        mrow[r] = -1e30f;
        lrow[r] = 0.f;
#pragma unroll
        for (int c = 0; c < 4; c++) o2[r][c] = 0ull;
    }

    for (int kt = 0; kt < SEQ / BKT; kt++) {
        __syncthreads();   // prior PV done reading Vs/Ps; also orders Qs on iter 0
        const int k0 = kt * BKT;
        for (int idx = tid; idx < BKT * (DHEAD / 4); idx += 256) {
            int j  = idx >> 5;
            int d4 = (idx & 31) << 2;
            float4 kv = *(const float4*)(Kn + (rowbase + k0 + j) * D_MODEL + hb + d4);
            KsT[(d4 + 0) * KTPAD + j] = kv.x;
            KsT[(d4 + 1) * KTPAD + j] = kv.y;
            KsT[(d4 + 2) * KTPAD + j] = kv.z;
            KsT[(d4 + 3) * KTPAD + j] = kv.w;
            float4 vv = *(const float4*)(V + (rowbase + k0 + j) * D_MODEL + hb + d4);
            *(float4*)(Vs + j * DHEAD + d4) = vv;
        }
        __syncthreads();

        // S = Q K^T   (4x4 per thread), d unrolled by 4, packed f32x2 over cols
        u64 s2[4][2];
#pragma unroll
        for (int r = 0; r < 4; r++) { s2[r][0] = 0ull; s2[r][1] = 0ull; }

#pragma unroll 2
        for (int d = 0; d < DHEAD; d += 4) {
            float4 qv[4], kv[4];
#pragma unroll
            for (int r = 0; r < 4; r++)
                qv[r] = *(const float4*)(Qs + (ty * 4 + r) * QPAD + d);
#pragma unroll
            for (int dd = 0; dd < 4; dd++)
                kv[dd] = *(const float4*)(KsT + (d + dd) * KTPAD + tx * 4);
#pragma unroll
            for (int dd = 0; dd < 4; dd++) {
                u64 kpA = f2_pack(kv[dd].x, kv[dd].y);
                u64 kpB = f2_pack(kv[dd].z, kv[dd].w);
#pragma unroll
                for (int r = 0; r < 4; r++) {
                    u64 qd = f2_dup(((const float*)&qv[r])[dd]);
                    f2_fma(s2[r][0], qd, kpA);
                    f2_fma(s2[r][1], qd, kpB);
                }
            }
        }

        // online softmax update (row reductions across the 16 tx lanes)
#pragma unroll
        for (int r = 0; r < 4; r++) {
            float s[4];
            f2_unpack(s2[r][0], s[0], s[1]);
            f2_unpack(s2[r][1], s[2], s[3]);
            float mx = fmaxf(fmaxf(s[0], s[1]), fmaxf(s[2], s[3]));
#pragma unroll
            for (int msk = 8; msk; msk >>= 1)
                mx = fmaxf(mx, __shfl_xor_sync(0xffffffffu, mx, msk));
            const float mnew = fmaxf(mrow[r], mx);
            const float corr = __expf(mrow[r] - mnew);
            float rs = 0.f;
#pragma unroll
            for (int c = 0; c < 4; c++) {
                float p = __expf(s[c] - mnew);
                Ps[(ty * 4 + r) * PPAD + tx * 4 + c] = p;
                rs += p;
            }
#pragma unroll
            for (int msk = 8; msk; msk >>= 1)
                rs += __shfl_xor_sync(0xffffffffu, rs, msk);
            lrow[r] = lrow[r] * corr + rs;
            mrow[r] = mnew;
            u64 cd = f2_dup(corr);
#pragma unroll
            for (int c = 0; c < 4; c++) o2[r][c] = f2_mul(o2[r][c], cd);
        }
        __syncthreads();

        // O += P V   (packed f32x2 over the 8 output cols)
#pragma unroll 4
        for (int k = 0; k < BKT; k++) {
            float4 v0 = *(const float4*)(Vs + k * DHEAD + tx * 8);
            float4 v1 = *(const float4*)(Vs + k * DHEAD + tx * 8 + 4);
            u64 vp[4];
            vp[0] = f2_pack(v0.x, v0.y); vp[1] = f2_pack(v0.z, v0.w);
            vp[2] = f2_pack(v1.x, v1.y); vp[3] = f2_pack(v1.z, v1.w);
#pragma unroll
            for (int r = 0; r < 4; r++) {
                u64 pd = f2_dup(Ps[(ty * 4 + r) * PPAD + k]);
                f2_fma(o2[r][0], pd, vp[0]);
                f2_fma(o2[r][1], pd, vp[1]);
                f2_fma(o2[r][2], pd, vp[2]);
                f2_fma(o2[r][3], pd, vp[3]);
            }
        }
    }

    // normalize and write Z in [b, s, h*dh] layout
#pragma unroll
    for (int r = 0; r < 4; r++) {
        const float inv = 1.f / lrow[r];
        float4 w0, w1;
        f2_unpack(o2[r][0], w0.x, w0.y);
        f2_unpack(o2[r][1], w0.z, w0.w);
        f2_unpack(o2[r][2], w1.x, w1.y);
        f2_unpack(o2[r][3], w1.z, w1.w);
        w0.x *= inv; w0.y *= inv; w0.z *= inv; w0.w *= inv;
        w1.x *= inv; w1.y *= inv; w1.z *= inv; w1.w *= inv;
        const size_t base = (rowbase + q0 + ty * 4 + r) * D_MODEL + hb + tx * 8;
        *(float4*)(Z + base)     = w0;
        *(float4*)(Z + base + 4) = w1;
    }
}

// ---------------------------------------------------------------------------
// Launch
// Inputs (metadata order): x, W_qkv, b_qkv, W_o, b_o, wq, wk   (all fp32)
// Output: [out | k_new | v_new], each MTOT*D_MODEL floats.
// ---------------------------------------------------------------------------
extern "C" void kernel_launch(void* const* d_in, const int* in_sizes, int n_in,
                              void* d_out, int out_size)
{
    const float* x    = (const float*)d_in[0];
    const float* Wqkv = (const float*)d_in[1];
    const float* bqkv = (const float*)d_in[2];
    const float* Wo   = (const float*)d_in[3];
    const float* bo   = (const float*)d_in[4];
    const float* wq   = (const float*)d_in[5];
    const float* wk   = (const float*)d_in[6];

    float* out  = (float*)d_out;
    float* kout = out + (size_t)OUTSZ;       // k_new (pre-norm)
    float* vout = out + (size_t)2 * OUTSZ;   // v_new

    float *qbuf = nullptr, *knbuf = nullptr, *zbuf = nullptr;
    cudaGetSymbolAddress((void**)&qbuf,  g_q);
    cudaGetSymbolAddress((void**)&knbuf, g_kn);
    cudaGetSymbolAddress((void**)&zbuf,  g_z);

    // 1) QKV projection: q -> scratch, k/v -> their output regions directly
    gemm_bias_nt<<<dim3(3 * D_MODEL / BN, MTOT / BM), 256>>>(
        x, Wqkv, bqkv, qbuf, kout, vout,
        MTOT, 3 * D_MODEL, D_MODEL, D_MODEL);

    // 2) per-head RMSNorm on q (in place) and k (into scratch)
    rmsnorm128<<<(MTOT * NHEADS) / 8, 256>>>(qbuf, qbuf, wq);
    rmsnorm128<<<(MTOT * NHEADS) / 8, 256>>>(kout, knbuf, wk);

    // 3) flash attention -> z scratch
    const int attn_smem = ATTN_SMEM_FLOATS * (int)sizeof(float);
    cudaFuncSetAttribute(attn_flash,
                         cudaFuncAttributeMaxDynamicSharedMemorySize, attn_smem);
    attn_flash<<<dim3(SEQ / BQ, NHEADS, BATCH), 256, attn_smem>>>(
        qbuf, knbuf, vout, zbuf);

    // 4) output projection
    gemm_bias_nt<<<dim3(D_MODEL / BN, MTOT / BM), 256>>>(
        zbuf, Wo, bo, out, out, out,
        MTOT, D_MODEL, D_MODEL, D_MODEL);
}

// round 11
// speedup vs baseline: 1.0001x; 1.0001x over previous
#include <cuda_runtime.h>

// ---------------------------------------------------------------------------
// Problem constants
// ---------------------------------------------------------------------------
#define D_MODEL 2048
#define NHEADS  16
#define DHEAD   128
#define SEQ     2048
#define BATCH   2
#define MTOT    (BATCH * SEQ)        // 4096 rows
#define OUTSZ   (MTOT * D_MODEL)     // 8388608 elements per output tensor

// Scratch buffers (no cudaMalloc allowed -> device globals)
__device__ float g_q [MTOT * D_MODEL];  // q  (then qn in-place)
__device__ float g_kn[MTOT * D_MODEL];  // normalized k
__device__ float g_z [MTOT * D_MODEL];  // attention output (pre out-proj)

// ---------------------------------------------------------------------------
// Packed fp32x2 helpers (Blackwell FFMA2 path: full-rate fp32)
// ---------------------------------------------------------------------------
typedef unsigned long long u64;

__device__ __forceinline__ u64 f2_pack(float lo, float hi) {
    u64 r; asm("mov.b64 %0, {%1, %2};" : "=l"(r) : "f"(lo), "f"(hi)); return r;
}
__device__ __forceinline__ u64 f2_dup(float x) { return f2_pack(x, x); }
__device__ __forceinline__ void f2_fma(u64& d, u64 a, u64 b) {
    asm("fma.rn.f32x2 %0, %1, %2, %0;" : "+l"(d) : "l"(a), "l"(b));
}
__device__ __forceinline__ u64 f2_mul(u64 a, u64 b) {
    u64 r; asm("mul.rn.f32x2 %0, %1, %2;" : "=l"(r) : "l"(a), "l"(b)); return r;
}
__device__ __forceinline__ void f2_unpack(u64 v, float& lo, float& hi) {
    asm("mov.b64 {%0, %1}, %2;" : "=f"(lo), "=f"(hi) : "l"(v));
}

// ---------------------------------------------------------------------------
// GEMM: C[m,n] = sum_k A[m,k] * B[n,k] + bias[n]     (A:[M,K], B:[N,K] row-major)
// Output routed into up-to-3 segment pointers of width segN each.
// BM=BN=128, BK=16, 256 threads, 8x8 per thread (4+64 split).
// Single-buffered smem, 2 CTAs/SM (cross-CTA latency overlap),
// packed f32x2 accumulators (pairs along n).
// ---------------------------------------------------------------------------
#define BM 128
#define BN 128
#define BK 16

__global__ __launch_bounds__(256, 2)
void gemm_bias_nt(const float* __restrict__ A, const float* __restrict__ B,
                  const float* __restrict__ bias,
                  float* __restrict__ out0, float* __restrict__ out1,
                  float* __restrict__ out2,
                  int M, int N, int K, int segN)
{
    __shared__ __align__(16) float As[BK][BM];
    __shared__ __align__(16) float Bs[BK][BN];

    const int tid = threadIdx.x;
    const int tx  = tid & 15;
    const int ty  = tid >> 4;
    const int m0  = blockIdx.y * BM;
    const int n0  = blockIdx.x * BN;

    const float* Ab = A + (size_t)m0 * K;
    const float* Bb = B + (size_t)n0 * K;

    u64 acc2[8][4];
#pragma unroll
    for (int i = 0; i < 8; i++)
#pragma unroll
        for (int j = 0; j < 4; j++) acc2[i][j] = 0ull;

    const int ntiles = K / BK;
    for (int t = 0; t < ntiles; t++) {
        const int k0 = t * BK;
#pragma unroll
        for (int i = 0; i < 2; i++) {
            int idx = tid + i * 256;
            int row = idx >> 2;
            int kg  = (idx & 3) << 2;
            float4 av = *(const float4*)(Ab + (size_t)row * K + k0 + kg);
            As[kg + 0][row] = av.x; As[kg + 1][row] = av.y;
            As[kg + 2][row] = av.z; As[kg + 3][row] = av.w;
            float4 bv = *(const float4*)(Bb + (size_t)row * K + k0 + kg);
            Bs[kg + 0][row] = bv.x; Bs[kg + 1][row] = bv.y;
            Bs[kg + 2][row] = bv.z; Bs[kg + 3][row] = bv.w;
        }
        __syncthreads();

#pragma unroll
        for (int kk = 0; kk < BK; kk++) {
            float4 a0 = *(const float4*)&As[kk][ty * 4];
            float4 a1 = *(const float4*)&As[kk][ty * 4 + 64];
            float4 b0 = *(const float4*)&Bs[kk][tx * 4];
            float4 b1 = *(const float4*)&Bs[kk][tx * 4 + 64];
            u64 bp[4];
            bp[0] = f2_pack(b0.x, b0.y); bp[1] = f2_pack(b0.z, b0.w);
            bp[2] = f2_pack(b1.x, b1.y); bp[3] = f2_pack(b1.z, b1.w);
            float av[8] = {a0.x, a0.y, a0.z, a0.w, a1.x, a1.y, a1.z, a1.w};
#pragma unroll
            for (int i = 0; i < 8; i++) {
                u64 ad = f2_dup(av[i]);
#pragma unroll
                for (int j = 0; j < 4; j++)
                    f2_fma(acc2[i][j], ad, bp[j]);
            }
        }
        __syncthreads();
    }

    // epilogue: bias + segmented store (each 128-wide block tile lies in one segment)
#pragma unroll
    for (int i = 0; i < 8; i++) {
        const int gm = m0 + ((i < 4) ? (ty * 4 + i) : (64 + ty * 4 + (i - 4)));
#pragma unroll
        for (int jh = 0; jh < 2; jh++) {
            const int gn  = n0 + tx * 4 + jh * 64;
            const int seg = gn / segN;
            float* o = (seg == 0) ? out0 : ((seg == 1) ? out1 : out2);
            float4 v;
            f2_unpack(acc2[i][jh * 2 + 0], v.x, v.y);
            f2_unpack(acc2[i][jh * 2 + 1], v.z, v.w);
            v.x += bias[gn + 0];
            v.y += bias[gn + 1];
            v.z += bias[gn + 2];
            v.w += bias[gn + 3];
            *(float4*)(o + (size_t)gm * segN + (gn - seg * segN)) = v;
        }
    }
}

// ---------------------------------------------------------------------------
// RMSNorm over contiguous 128-float vectors: out = x * rsqrt(mean(x^2)+eps) * w
// one warp per vector
// ---------------------------------------------------------------------------
__global__ __launch_bounds__(256)
void rmsnorm128(const float* __restrict__ in, float* __restrict__ out,
                const float* __restrict__ w)
{
    const int row  = blockIdx.x * 8 + (threadIdx.x >> 5);
    const int lane = threadIdx.x & 31;
    const size_t base = (size_t)row * DHEAD + lane * 4;
    float4 xv = *(const float4*)(in + base);
    float ss = xv.x * xv.x + xv.y * xv.y + xv.z * xv.z + xv.w * xv.w;
#pragma unroll
    for (int msk = 16; msk; msk >>= 1)
        ss += __shfl_xor_sync(0xffffffffu, ss, msk);
    const float r = rsqrtf(ss * (1.0f / 128.0f) + 1e-6f);
    float4 wv = *(const float4*)(w + lane * 4);
    float4 ov;
    ov.x = xv.x * r * wv.x;
    ov.y = xv.y * r * wv.y;
    ov.z = xv.z * r * wv.z;
    ov.w = xv.w * r * wv.w;
    *(float4*)(out + base) = ov;
}

// ---------------------------------------------------------------------------
// Flash attention (non-causal, scale = 1.0), fp32 with f32x2 inner loops.
// Grid: (SEQ/BQ, NHEADS, BATCH). Block: 256 threads (16x16).
// ---------------------------------------------------------------------------
#define BQ    64
#define BKT   64
#define QPAD  132   // Qs row stride (floats)
#define KTPAD 68    // KsT row stride (floats)
#define PPAD  65    // Ps row stride (floats)

#define ATTN_SMEM_FLOATS (BQ * QPAD + DHEAD * KTPAD + BKT * DHEAD + BQ * PPAD)

__global__ __launch_bounds__(256, 1)
void attn_flash(const float* __restrict__ Q, const float* __restrict__ Kn,
                const float* __restrict__ V, float* __restrict__ Z)
{
    extern __shared__ __align__(16) float sm[];
    float* Qs  = sm;                        // [BQ][QPAD]
    float* KsT = Qs  + BQ * QPAD;           // [DHEAD][KTPAD]  (transposed K)
    float* Vs  = KsT + DHEAD * KTPAD;       // [BKT][DHEAD]
    float* Ps  = Vs  + BKT * DHEAD;         // [BQ][PPAD]

    const int tid = threadIdx.x;
    const int tx  = tid & 15;
    const int ty  = tid >> 4;
    const int qt  = blockIdx.x;
    const int h   = blockIdx.y;
    const int b   = blockIdx.z;

    const size_t rowbase = (size_t)b * SEQ;
    const int    hb      = h * DHEAD;
    const int    q0      = qt * BQ;

    // Load Q tile (reused for all K tiles)
    for (int idx = tid; idx < BQ * (DHEAD / 4); idx += 256) {
        int i  = idx >> 5;
        int d4 = (idx & 31) << 2;
        float4 v = *(const float4*)(Q + (rowbase + q0 + i) * D_MODEL + hb + d4);
        *(float4*)(Qs + i * QPAD + d4) = v;
    }

    u64 o2[4][4];   // 4 rows x 8 cols packed in pairs
    float mrow[4], lrow[4];
#pragma unroll
    for (int r = 0; r < 4; r++) {
        mrow[r] = -1e30f;
        lrow[r] = 0.f;
#pragma unroll
        for (int c = 0; c < 4; c++) o2[r][c] = 0ull;
    }

    for (int kt = 0; kt < SEQ / BKT; kt++) {
        __syncthreads();   // prior PV done reading Vs/Ps; also orders Qs on iter 0
        const int k0 = kt * BKT;
        for (int idx = tid; idx < BKT * (DHEAD / 4); idx += 256) {
            int j  = idx >> 5;
            int d4 = (idx & 31) << 2;
            float4 kv = *(const float4*)(Kn + (rowbase + k0 + j) * D_MODEL + hb + d4);
            KsT[(d4 + 0) * KTPAD + j] = kv.x;
            KsT[(d4 + 1) * KTPAD + j] = kv.y;
            KsT[(d4 + 2) * KTPAD + j] = kv.z;
            KsT[(d4 + 3) * KTPAD + j] = kv.w;
            float4 vv = *(const float4*)(V + (rowbase + k0 + j) * D_MODEL + hb + d4);
            *(float4*)(Vs + j * DHEAD + d4) = vv;
        }
        __syncthreads();

        // S = Q K^T   (4x4 per thread), d unrolled by 4, packed f32x2 over cols
        u64 s2[4][2];
#pragma unroll
        for (int r = 0; r < 4; r++) { s2[r][0] = 0ull; s2[r][1] = 0ull; }

#pragma unroll 2
        for (int d = 0; d < DHEAD; d += 4) {
            float4 qv[4], kv[4];
#pragma unroll
            for (int r = 0; r < 4; r++)
                qv[r] = *(const float4*)(Qs + (ty * 4 + r) * QPAD + d);
#pragma unroll
            for (int dd = 0; dd < 4; dd++)
                kv[dd] = *(const float4*)(KsT + (d + dd) * KTPAD + tx * 4);
#pragma unroll
            for (int dd = 0; dd < 4; dd++) {
                u64 kpA = f2_pack(kv[dd].x, kv[dd].y);
                u64 kpB = f2_pack(kv[dd].z, kv[dd].w);
#pragma unroll
                for (int r = 0; r < 4; r++) {
                    u64 qd = f2_dup(((const float*)&qv[r])[dd]);
                    f2_fma(s2[r][0], qd, kpA);
                    f2_fma(s2[r][1], qd, kpB);
                }
            }
        }

        // online softmax update (row reductions across the 16 tx lanes)
#pragma unroll
        for (int r = 0; r < 4; r++) {
            float s[4];
            f2_unpack(s2[r][0], s[0], s[1]);
            f2_unpack(s2[r][1], s[2], s[3]);
            float mx = fmaxf(fmaxf(s[0], s[1]), fmaxf(s[2], s[3]));
#pragma unroll
            for (int msk = 8; msk; msk >>= 1)
                mx = fmaxf(mx, __shfl_xor_sync(0xffffffffu, mx, msk));
            const float mnew = fmaxf(mrow[r], mx);
            const float corr = __expf(mrow[r] - mnew);
            float rs = 0.f;
#pragma unroll
            for (int c = 0; c < 4; c++) {
                float p = __expf(s[c] - mnew);
                Ps[(ty * 4 + r) * PPAD + tx * 4 + c] = p;
                rs += p;
            }
#pragma unroll
            for (int msk = 8; msk; msk >>= 1)
                rs += __shfl_xor_sync(0xffffffffu, rs, msk);
            lrow[r] = lrow[r] * corr + rs;
            mrow[r] = mnew;
            u64 cd = f2_dup(corr);
#pragma unroll
            for (int c = 0; c < 4; c++) o2[r][c] = f2_mul(o2[r][c], cd);
        }
        __syncthreads();

        // O += P V   (packed f32x2 over the 8 output cols)
#pragma unroll 4
        for (int k = 0; k < BKT; k++) {
            float4 v0 = *(const float4*)(Vs + k * DHEAD + tx * 8);
            float4 v1 = *(const float4*)(Vs + k * DHEAD + tx * 8 + 4);
            u64 vp[4];
            vp[0] = f2_pack(v0.x, v0.y); vp[1] = f2_pack(v0.z, v0.w);
            vp[2] = f2_pack(v1.x, v1.y); vp[3] = f2_pack(v1.z, v1.w);
#pragma unroll
            for (int r = 0; r < 4; r++) {
                u64 pd = f2_dup(Ps[(ty * 4 + r) * PPAD + k]);
                f2_fma(o2[r][0], pd, vp[0]);
                f2_fma(o2[r][1], pd, vp[1]);
                f2_fma(o2[r][2], pd, vp[2]);
                f2_fma(o2[r][3], pd, vp[3]);
            }
        }
    }

    // normalize and write Z in [b, s, h*dh] layout
#pragma unroll
    for (int r = 0; r < 4; r++) {
        const float inv = 1.f / lrow[r];
        float4 w0, w1;
        f2_unpack(o2[r][0], w0.x, w0.y);
        f2_unpack(o2[r][1], w0.z, w0.w);
        f2_unpack(o2[r][2], w1.x, w1.y);
        f2_unpack(o2[r][3], w1.z, w1.w);
        w0.x *= inv; w0.y *= inv; w0.z *= inv; w0.w *= inv;
        w1.x *= inv; w1.y *= inv; w1.z *= inv; w1.w *= inv;
        const size_t base = (rowbase + q0 + ty * 4 + r) * D_MODEL + hb + tx * 8;
        *(float4*)(Z + base)     = w0;
        *(float4*)(Z + base + 4) = w1;
    }
}

// ---------------------------------------------------------------------------
// Launch
// Inputs (metadata order): x, W_qkv, b_qkv, W_o, b_o, wq, wk   (all fp32)
// Output: [out | k_new | v_new], each MTOT*D_MODEL floats.
// ---------------------------------------------------------------------------
extern "C" void kernel_launch(void* const* d_in, const int* in_sizes, int n_in,
                              void* d_out, int out_size)
{
    const float* x    = (const float*)d_in[0];
    const float* Wqkv = (const float*)d_in[1];
    const float* bqkv = (const float*)d_in[2];
    const float* Wo   = (const float*)d_in[3];
    const float* bo   = (const float*)d_in[4];
    const float* wq   = (const float*)d_in[5];
    const float* wk   = (const float*)d_in[6];

    float* out  = (float*)d_out;
    float* kout = out + (size_t)OUTSZ;       // k_new (pre-norm)
    float* vout = out + (size_t)2 * OUTSZ;   // v_new

    float *qbuf = nullptr, *knbuf = nullptr, *zbuf = nullptr;
    cudaGetSymbolAddress((void**)&qbuf,  g_q);
    cudaGetSymbolAddress((void**)&knbuf, g_kn);
    cudaGetSymbolAddress((void**)&zbuf,  g_z);

    // 1) QKV projection: q -> scratch, k/v -> their output regions directly
    gemm_bias_nt<<<dim3(3 * D_MODEL / BN, MTOT / BM), 256>>>(
        x, Wqkv, bqkv, qbuf, kout, vout,
        MTOT, 3 * D_MODEL, D_MODEL, D_MODEL);

    // 2) per-head RMSNorm on q (in place) and k (into scratch)
    rmsnorm128<<<(MTOT * NHEADS) / 8, 256>>>(qbuf, qbuf, wq);
    rmsnorm128<<<(MTOT * NHEADS) / 8, 256>>>(kout, knbuf, wk);

    // 3) flash attention -> z scratch
    const int attn_smem = ATTN_SMEM_FLOATS * (int)sizeof(float);
    cudaFuncSetAttribute(attn_flash,
                         cudaFuncAttributeMaxDynamicSharedMemorySize, attn_smem);
    attn_flash<<<dim3(SEQ / BQ, NHEADS, BATCH), 256, attn_smem>>>(
        qbuf, knbuf, vout, zbuf);

    // 4) output projection
    gemm_bias_nt<<<dim3(D_MODEL / BN, MTOT / BM), 256>>>(
        zbuf, Wo, bo, out, out, out,
        MTOT, D_MODEL, D_MODEL, D_MODEL);
}

// round 14
// speedup vs baseline: 1.4687x; 1.4686x over previous
#include <cuda_runtime.h>
#include <cuda_bf16.h>
#include <cstdint>

// ---------------------------------------------------------------------------
// Problem constants
// ---------------------------------------------------------------------------
#define D_MODEL 2048
#define NHEADS  16
#define DHEAD   128
#define SEQ     2048
#define BATCH   2
#define MTOT    (BATCH * SEQ)        // 4096 rows
#define OUTSZ   (MTOT * D_MODEL)     // 8388608 elements per output tensor

// Scratch buffers (no cudaMalloc allowed -> device globals)
__device__ float g_q [MTOT * D_MODEL];            // q  (then qn in-place)
__device__ float g_kn[MTOT * D_MODEL];            // normalized k
__device__ float g_z [MTOT * D_MODEL];            // attention output
__device__ __nv_bfloat16 g_ahi[MTOT * D_MODEL];   // A-hi (x, then z)
__device__ __nv_bfloat16 g_alo[MTOT * D_MODEL];   // A-lo
__device__ __nv_bfloat16 g_bhi[3 * D_MODEL * D_MODEL]; // B-hi (Wqkv, then Wo)
__device__ __nv_bfloat16 g_blo[3 * D_MODEL * D_MODEL]; // B-lo

typedef unsigned long long u64;

// ---------------------------------------------------------------------------
// Packed fp32x2 helpers (attention inner loops)
// ---------------------------------------------------------------------------
__device__ __forceinline__ u64 f2_pack(float lo, float hi) {
    u64 r; asm("mov.b64 %0, {%1, %2};" : "=l"(r) : "f"(lo), "f"(hi)); return r;
}
__device__ __forceinline__ u64 f2_dup(float x) { return f2_pack(x, x); }
__device__ __forceinline__ void f2_fma(u64& d, u64 a, u64 b) {
    asm("fma.rn.f32x2 %0, %1, %2, %0;" : "+l"(d) : "l"(a), "l"(b));
}
__device__ __forceinline__ u64 f2_mul(u64 a, u64 b) {
    u64 r; asm("mul.rn.f32x2 %0, %1, %2;" : "=l"(r) : "l"(a), "l"(b)); return r;
}
__device__ __forceinline__ void f2_unpack(u64 v, float& lo, float& hi) {
    asm("mov.b64 {%0, %1}, %2;" : "=f"(lo), "=f"(hi) : "l"(v));
}

// ---------------------------------------------------------------------------
// Base-target tensor-core helpers (sm_80+ ISA: ldmatrix / mma.sync / cp.async)
// ---------------------------------------------------------------------------
__device__ __forceinline__ uint32_t smem_u32(const void* p) {
    uint32_t a;
    asm("{ .reg .u64 t; cvta.to.shared.u64 t, %1; cvt.u32.u64 %0, t; }"
        : "=r"(a) : "l"(p));
    return a;
}
__device__ __forceinline__ void ldsm_x4(uint32_t& r0, uint32_t& r1,
                                        uint32_t& r2, uint32_t& r3, uint32_t addr) {
    asm volatile("ldmatrix.sync.aligned.m8n8.x4.shared.b16 {%0,%1,%2,%3}, [%4];"
                 : "=r"(r0), "=r"(r1), "=r"(r2), "=r"(r3) : "r"(addr));
}
__device__ __forceinline__ void mma16816(float* d, const uint32_t* a,
                                         const uint32_t* b) {
    asm volatile("mma.sync.aligned.m16n8k16.row.col.f32.bf16.bf16.f32 "
                 "{%0,%1,%2,%3}, {%4,%5,%6,%7}, {%8,%9}, {%0,%1,%2,%3};"
                 : "+f"(d[0]), "+f"(d[1]), "+f"(d[2]), "+f"(d[3])
                 : "r"(a[0]), "r"(a[1]), "r"(a[2]), "r"(a[3]),
                   "r"(b[0]), "r"(b[1]));
}
__device__ __forceinline__ void cp_async16(uint32_t dst, const void* src) {
    asm volatile("cp.async.cg.shared.global [%0], [%1], 16;"
                 :: "r"(dst), "l"(src) : "memory");
}
__device__ __forceinline__ void cp_commit() {
    asm volatile("cp.async.commit_group;" ::: "memory");
}
template <int N>
__device__ __forceinline__ void cp_wait() {
    asm volatile("cp.async.wait_group %0;" :: "n"(N) : "memory");
}

// ---------------------------------------------------------------------------
// fp32 -> (bf16 hi, bf16 lo) split, vectorized
// ---------------------------------------------------------------------------
__global__ __launch_bounds__(256)
void split_f32(const float* __restrict__ src, __nv_bfloat16* __restrict__ hi,
               __nv_bfloat16* __restrict__ lo, int n)
{
    int i = (blockIdx.x * 256 + threadIdx.x) * 4;
    if (i >= n) return;
    float4 x = *(const float4*)(src + i);
    __nv_bfloat16 h0 = __float2bfloat16(x.x);
    __nv_bfloat16 h1 = __float2bfloat16(x.y);
    __nv_bfloat16 h2 = __float2bfloat16(x.z);
    __nv_bfloat16 h3 = __float2bfloat16(x.w);
    __nv_bfloat16 l0 = __float2bfloat16(x.x - __bfloat162float(h0));
    __nv_bfloat16 l1 = __float2bfloat16(x.y - __bfloat162float(h1));
    __nv_bfloat16 l2 = __float2bfloat16(x.z - __bfloat162float(h2));
    __nv_bfloat16 l3 = __float2bfloat16(x.w - __bfloat162float(h3));
    uint2 hv, lv;
    hv.x = (uint32_t)__bfloat16_as_ushort(h0) | ((uint32_t)__bfloat16_as_ushort(h1) << 16);
    hv.y = (uint32_t)__bfloat16_as_ushort(h2) | ((uint32_t)__bfloat16_as_ushort(h3) << 16);
    lv.x = (uint32_t)__bfloat16_as_ushort(l0) | ((uint32_t)__bfloat16_as_ushort(l1) << 16);
    lv.y = (uint32_t)__bfloat16_as_ushort(l2) | ((uint32_t)__bfloat16_as_ushort(l3) << 16);
    *(uint2*)(hi + i) = hv;
    *(uint2*)(lo + i) = lv;
}

// ---------------------------------------------------------------------------
// HMMA (mma.sync) GEMM with bf16x3 fp32 emulation.
// C[m,n] = sum_k A[m,k]*B[n,k] + bias[n].  A:[M,2048], B:[N,2048] row-major,
// pre-split into (hi,lo) bf16. 128x128 tile per CTA, BK=32, cp.async
// double-buffered. 8 warps in 2(M)x4(N); warp tile 64x32.
// D += Ahi*Bhi + Ahi*Blo + Alo*Bhi  (lo*lo dropped, ~2^-18 relative).
// ---------------------------------------------------------------------------
#define GK    2048
#define BK2   32
#define APAD  40                            // smem row stride (bf16 elems)
#define PART_ELE (128 * APAD)               // elems per part (A/B, hi/lo)
#define STAGE_B  (4 * PART_ELE * 2)         // bytes per stage = 40960
#define GEMM_SMEM (2 * STAGE_B)             // 81920 bytes

__global__ __launch_bounds__(256, 2)
void gemm_mma(const __nv_bfloat16* __restrict__ Ahi, const __nv_bfloat16* __restrict__ Alo,
              const __nv_bfloat16* __restrict__ Bhi, const __nv_bfloat16* __restrict__ Blo,
              const float* __restrict__ bias,
              float* __restrict__ out0, float* __restrict__ out1,
              float* __restrict__ out2, int segN)
{
    extern __shared__ __align__(16) __nv_bfloat16 smem[];
    const uint32_t sb = smem_u32(smem);

    const int tid    = threadIdx.x;
    const int wid    = tid >> 5;
    const int lane   = tid & 31;
    const int warp_m = wid >> 2;            // 0..1
    const int warp_n = wid & 3;             // 0..3
    const int wm0    = warp_m * 64;
    const int wn0    = warp_n * 32;
    const int m0     = blockIdx.y * 128;
    const int n0     = blockIdx.x * 128;

    const __nv_bfloat16* gsrc[4];
    gsrc[0] = Ahi + (size_t)m0 * GK;
    gsrc[1] = Alo + (size_t)m0 * GK;
    gsrc[2] = Bhi + (size_t)n0 * GK;
    gsrc[3] = Blo + (size_t)n0 * GK;

    // per-thread load slots: 512 16B-chunks per part, 2 per thread
    const int lrow = tid >> 2;              // 0..63? no: idx>>2 below
    (void)lrow;

    float acc[4][4][4];
#pragma unroll
    for (int mi = 0; mi < 4; mi++)
#pragma unroll
        for (int ni = 0; ni < 4; ni++)
#pragma unroll
            for (int e = 0; e < 4; e++) acc[mi][ni][e] = 0.f;

    // ---- pipelined load helper (issues cp.async for one k-tile) ----
    auto load_tile = [&](int t, int buf) {
        const uint32_t sbase = sb + buf * STAGE_B;
#pragma unroll
        for (int p = 0; p < 4; p++) {
            const __nv_bfloat16* s = gsrc[p] + t * BK2;
            const uint32_t dbase = sbase + p * (PART_ELE * 2);
#pragma unroll
            for (int i = 0; i < 2; i++) {
                int idx = tid + i * 256;            // 0..511
                int r   = idx >> 2;                 // row 0..127
                int c   = (idx & 3) * 8;            // bf16 col {0,8,16,24}
                cp_async16(dbase + (r * APAD + c) * 2,
                           s + (size_t)r * GK + c);
            }
        }
        cp_commit();
    };

    load_tile(0, 0);

    const int ntiles = GK / BK2;            // 64
    for (int t = 0; t < ntiles; t++) {
        const int buf = t & 1;
        if (t + 1 < ntiles) load_tile(t + 1, buf ^ 1);
        if (t + 1 < ntiles) cp_wait<1>(); else cp_wait<0>();
        __syncthreads();

        const uint32_t aHiB = sb + buf * STAGE_B;
        const uint32_t aLoB = aHiB + PART_ELE * 2;
        const uint32_t bHiB = aHiB + 2 * PART_ELE * 2;
        const uint32_t bLoB = aHiB + 3 * PART_ELE * 2;

#pragma unroll
        for (int ks = 0; ks < 2; ks++) {
            // B fragments for all 4 n-tiles (2 x ldmatrix.x4, hi+lo)
            const int brow = wn0 + ((lane >> 4) & 1) * 8 + (lane & 7);
            const int bkof = ks * 16 + ((lane >> 3) & 1) * 8;
            uint32_t bh[2][4], bl[2][4];
#pragma unroll
            for (int ni2 = 0; ni2 < 2; ni2++) {
                const uint32_t boff = ((brow + ni2 * 16) * APAD + bkof) * 2;
                ldsm_x4(bh[ni2][0], bh[ni2][1], bh[ni2][2], bh[ni2][3], bHiB + boff);
                ldsm_x4(bl[ni2][0], bl[ni2][1], bl[ni2][2], bl[ni2][3], bLoB + boff);
            }
            // A fragments per m-tile, then 12 MMAs each
            const int arow = wm0 + (lane & 15);
            const int akof = ks * 16 + (lane >> 4) * 8;
#pragma unroll
            for (int mi = 0; mi < 4; mi++) {
                const uint32_t aoff = ((arow + mi * 16) * APAD + akof) * 2;
                uint32_t ah[4], al[4];
                ldsm_x4(ah[0], ah[1], ah[2], ah[3], aHiB + aoff);
                ldsm_x4(al[0], al[1], al[2], al[3], aLoB + aoff);
#pragma unroll
                for (int ni = 0; ni < 4; ni++) {
                    const uint32_t* bhp = &bh[ni >> 1][(ni & 1) * 2];
                    const uint32_t* blp = &bl[ni >> 1][(ni & 1) * 2];
                    mma16816(acc[mi][ni], ah, bhp);
                    mma16816(acc[mi][ni], ah, blp);
                    mma16816(acc[mi][ni], al, bhp);
                }
            }
        }
        __syncthreads();
    }

    // ---- epilogue: bias + segmented store ----
    const int seg = n0 / segN;
    float* o = (seg == 0) ? out0 : ((seg == 1) ? out1 : out2);
    const int nseg0 = n0 - seg * segN;
#pragma unroll
    for (int mi = 0; mi < 4; mi++) {
        const int gm = m0 + wm0 + mi * 16 + (lane >> 2);
#pragma unroll
        for (int ni = 0; ni < 4; ni++) {
            const int gn  = n0 + wn0 + ni * 8 + (lane & 3) * 2;
            const int cn  = nseg0 + (gn - n0);
            float2 bv = *(const float2*)(bias + gn);
            float2 v0, v1;
            v0.x = acc[mi][ni][0] + bv.x;
            v0.y = acc[mi][ni][1] + bv.y;
            v1.x = acc[mi][ni][2] + bv.x;
            v1.y = acc[mi][ni][3] + bv.y;
            *(float2*)(o + (size_t)gm * segN + cn)       = v0;
            *(float2*)(o + (size_t)(gm + 8) * segN + cn) = v1;
        }
    }
}

// ---------------------------------------------------------------------------
// RMSNorm over contiguous 128-float vectors
// ---------------------------------------------------------------------------
__global__ __launch_bounds__(256)
void rmsnorm128(const float* __restrict__ in, float* __restrict__ out,
                const float* __restrict__ w)
{
    const int row  = blockIdx.x * 8 + (threadIdx.x >> 5);
    const int lane = threadIdx.x & 31;
    const size_t base = (size_t)row * DHEAD + lane * 4;
    float4 xv = *(const float4*)(in + base);
    float ss = xv.x * xv.x + xv.y * xv.y + xv.z * xv.z + xv.w * xv.w;
#pragma unroll
    for (int msk = 16; msk; msk >>= 1)
        ss += __shfl_xor_sync(0xffffffffu, ss, msk);
    const float r = rsqrtf(ss * (1.0f / 128.0f) + 1e-6f);
    float4 wv = *(const float4*)(w + lane * 4);
    float4 ov;
    ov.x = xv.x * r * wv.x;
    ov.y = xv.y * r * wv.y;
    ov.z = xv.z * r * wv.z;
    ov.w = xv.w * r * wv.w;
    *(float4*)(out + base) = ov;
}

// ---------------------------------------------------------------------------
// Flash attention (non-causal, scale = 1.0), fp32 with f32x2 inner loops.
// (unchanged from passing R8 version)
// ---------------------------------------------------------------------------
#define BQ    64
#define BKT   64
#define QPAD  132
#define KTPAD 68
#define PPAD  65
#define ATTN_SMEM_FLOATS (BQ * QPAD + DHEAD * KTPAD + BKT * DHEAD + BQ * PPAD)

__global__ __launch_bounds__(256, 1)
void attn_flash(const float* __restrict__ Q, const float* __restrict__ Kn,
                const float* __restrict__ V, float* __restrict__ Z)
{
    extern __shared__ __align__(16) float sm[];
    float* Qs  = sm;
    float* KsT = Qs  + BQ * QPAD;
    float* Vs  = KsT + DHEAD * KTPAD;
    float* Ps  = Vs  + BKT * DHEAD;

    const int tid = threadIdx.x;
    const int tx  = tid & 15;
    const int ty  = tid >> 4;
    const int qt  = blockIdx.x;
    const int h   = blockIdx.y;
    const int b   = blockIdx.z;

    const size_t rowbase = (size_t)b * SEQ;
    const int    hb      = h * DHEAD;
    const int    q0      = qt * BQ;

    for (int idx = tid; idx < BQ * (DHEAD / 4); idx += 256) {
        int i  = idx >> 5;
        int d4 = (idx & 31) << 2;
        float4 v = *(const float4*)(Q + (rowbase + q0 + i) * D_MODEL + hb + d4);
        *(float4*)(Qs + i * QPAD + d4) = v;
    }

    u64 o2[4][4];
    float mrow[4], lrow[4];
#pragma unroll
    for (int r = 0; r < 4; r++) {
        mrow[r] = -1e30f;
        lrow[r] = 0.f;
#pragma unroll
        for (int c = 0; c < 4; c++) o2[r][c] = 0ull;
    }

    for (int kt = 0; kt < SEQ / BKT; kt++) {
        __syncthreads();
        const int k0 = kt * BKT;
        for (int idx = tid; idx < BKT * (DHEAD / 4); idx += 256) {
            int j  = idx >> 5;
            int d4 = (idx & 31) << 2;
            float4 kv = *(const float4*)(Kn + (rowbase + k0 + j) * D_MODEL + hb + d4);
            KsT[(d4 + 0) * KTPAD + j] = kv.x;
            KsT[(d4 + 1) * KTPAD + j] = kv.y;
            KsT[(d4 + 2) * KTPAD + j] = kv.z;
            KsT[(d4 + 3) * KTPAD + j] = kv.w;
            float4 vv = *(const float4*)(V + (rowbase + k0 + j) * D_MODEL + hb + d4);
            *(float4*)(Vs + j * DHEAD + d4) = vv;
        }
        __syncthreads();

        u64 s2[4][2];
#pragma unroll
        for (int r = 0; r < 4; r++) { s2[r][0] = 0ull; s2[r][1] = 0ull; }

#pragma unroll 2
        for (int d = 0; d < DHEAD; d += 4) {
            float4 qv[4], kv[4];
#pragma unroll
            for (int r = 0; r < 4; r++)
                qv[r] = *(const float4*)(Qs + (ty * 4 + r) * QPAD + d);
#pragma unroll
            for (int dd = 0; dd < 4; dd++)
                kv[dd] = *(const float4*)(KsT + (d + dd) * KTPAD + tx * 4);
#pragma unroll
            for (int dd = 0; dd < 4; dd++) {
                u64 kpA = f2_pack(kv[dd].x, kv[dd].y);
                u64 kpB = f2_pack(kv[dd].z, kv[dd].w);
#pragma unroll
                for (int r = 0; r < 4; r++) {
                    u64 qd = f2_dup(((const float*)&qv[r])[dd]);
                    f2_fma(s2[r][0], qd, kpA);
                    f2_fma(s2[r][1], qd, kpB);
                }
            }
        }

#pragma unroll
        for (int r = 0; r < 4; r++) {
            float s[4];
            f2_unpack(s2[r][0], s[0], s[1]);
            f2_unpack(s2[r][1], s[2], s[3]);
            float mx = fmaxf(fmaxf(s[0], s[1]), fmaxf(s[2], s[3]));
#pragma unroll
            for (int msk = 8; msk; msk >>= 1)
                mx = fmaxf(mx, __shfl_xor_sync(0xffffffffu, mx, msk));
            const float mnew = fmaxf(mrow[r], mx);
            const float corr = __expf(mrow[r] - mnew);
            float rs = 0.f;
#pragma unroll
            for (int c = 0; c < 4; c++) {
                float p = __expf(s[c] - mnew);
                Ps[(ty * 4 + r) * PPAD + tx * 4 + c] = p;
                rs += p;
            }
#pragma unroll
            for (int msk = 8; msk; msk >>= 1)
                rs += __shfl_xor_sync(0xffffffffu, rs, msk);
            lrow[r] = lrow[r] * corr + rs;
            mrow[r] = mnew;
            u64 cd = f2_dup(corr);
#pragma unroll
            for (int c = 0; c < 4; c++) o2[r][c] = f2_mul(o2[r][c], cd);
        }
        __syncthreads();

#pragma unroll 4
        for (int k = 0; k < BKT; k++) {
            float4 v0 = *(const float4*)(Vs + k * DHEAD + tx * 8);
            float4 v1 = *(const float4*)(Vs + k * DHEAD + tx * 8 + 4);
            u64 vp[4];
            vp[0] = f2_pack(v0.x, v0.y); vp[1] = f2_pack(v0.z, v0.w);
            vp[2] = f2_pack(v1.x, v1.y); vp[3] = f2_pack(v1.z, v1.w);
#pragma unroll
            for (int r = 0; r < 4; r++) {
                u64 pd = f2_dup(Ps[(ty * 4 + r) * PPAD + k]);
                f2_fma(o2[r][0], pd, vp[0]);
                f2_fma(o2[r][1], pd, vp[1]);
                f2_fma(o2[r][2], pd, vp[2]);
                f2_fma(o2[r][3], pd, vp[3]);
            }
        }
    }

#pragma unroll
    for (int r = 0; r < 4; r++) {
        const float inv = 1.f / lrow[r];
        float4 w0, w1;
        f2_unpack(o2[r][0], w0.x, w0.y);
        f2_unpack(o2[r][1], w0.z, w0.w);
        f2_unpack(o2[r][2], w1.x, w1.y);
        f2_unpack(o2[r][3], w1.z, w1.w);
        w0.x *= inv; w0.y *= inv; w0.z *= inv; w0.w *= inv;
        w1.x *= inv; w1.y *= inv; w1.z *= inv; w1.w *= inv;
        const size_t base = (rowbase + q0 + ty * 4 + r) * D_MODEL + hb + tx * 8;
        *(float4*)(Z + base)     = w0;
        *(float4*)(Z + base + 4) = w1;
    }
}

// ---------------------------------------------------------------------------
// Launch
// ---------------------------------------------------------------------------
extern "C" void kernel_launch(void* const* d_in, const int* in_sizes, int n_in,
                              void* d_out, int out_size)
{
    const float* x    = (const float*)d_in[0];
    const float* Wqkv = (const float*)d_in[1];
    const float* bqkv = (const float*)d_in[2];
    const float* Wo   = (const float*)d_in[3];
    const float* bo   = (const float*)d_in[4];
    const float* wq   = (const float*)d_in[5];
    const float* wk   = (const float*)d_in[6];

    float* out  = (float*)d_out;
    float* kout = out + (size_t)OUTSZ;       // k_new (pre-norm)
    float* vout = out + (size_t)2 * OUTSZ;   // v_new

    float *qbuf, *knbuf, *zbuf;
    __nv_bfloat16 *ahi, *alo, *bhi, *blo;
    cudaGetSymbolAddress((void**)&qbuf,  g_q);
    cudaGetSymbolAddress((void**)&knbuf, g_kn);
    cudaGetSymbolAddress((void**)&zbuf,  g_z);
    cudaGetSymbolAddress((void**)&ahi,   g_ahi);
    cudaGetSymbolAddress((void**)&alo,   g_alo);
    cudaGetSymbolAddress((void**)&bhi,   g_bhi);
    cudaGetSymbolAddress((void**)&blo,   g_blo);

    cudaFuncSetAttribute(gemm_mma,
                         cudaFuncAttributeMaxDynamicSharedMemorySize, GEMM_SMEM);

    // 1) split x and Wqkv into bf16 hi/lo
    split_f32<<<OUTSZ / 1024, 256>>>(x, ahi, alo, OUTSZ);
    split_f32<<<(3 * D_MODEL * D_MODEL) / 1024, 256>>>(Wqkv, bhi, blo,
                                                       3 * D_MODEL * D_MODEL);

    // 2) QKV projection on tensor cores: q->scratch, k/v -> output regions
    gemm_mma<<<dim3(3 * D_MODEL / 128, MTOT / 128), 256, GEMM_SMEM>>>(
        ahi, alo, bhi, blo, bqkv, qbuf, kout, vout, D_MODEL);

    // 3) per-head RMSNorm on q (in place) and k (into scratch)
    rmsnorm128<<<(MTOT * NHEADS) / 8, 256>>>(qbuf, qbuf, wq);
    rmsnorm128<<<(MTOT * NHEADS) / 8, 256>>>(kout, knbuf, wk);

    // 4) flash attention -> z scratch
    const int attn_smem = ATTN_SMEM_FLOATS * (int)sizeof(float);
    cudaFuncSetAttribute(attn_flash,
                         cudaFuncAttributeMaxDynamicSharedMemorySize, attn_smem);
    attn_flash<<<dim3(SEQ / BQ, NHEADS, BATCH), 256, attn_smem>>>(
        qbuf, knbuf, vout, zbuf);

    // 5) split z and Wo, then output projection on tensor cores
    split_f32<<<OUTSZ / 1024, 256>>>(zbuf, ahi, alo, OUTSZ);
    split_f32<<<(D_MODEL * D_MODEL) / 1024, 256>>>(Wo, bhi, blo,
                                                   D_MODEL * D_MODEL);
    gemm_mma<<<dim3(D_MODEL / 128, MTOT / 128), 256, GEMM_SMEM>>>(
        ahi, alo, bhi, blo, bo, out, out, out, D_MODEL);
}

// round 15
// speedup vs baseline: 3.0594x; 2.0831x over previous
#include <cuda_runtime.h>
#include <cuda_bf16.h>
#include <cstdint>

// ---------------------------------------------------------------------------
// Problem constants
// ---------------------------------------------------------------------------
#define D_MODEL 2048
#define NHEADS  16
#define DHEAD   128
#define SEQ     2048
#define BATCH   2
#define MTOT    (BATCH * SEQ)        // 4096 rows
#define OUTSZ   (MTOT * D_MODEL)     // 8388608 elements per output tensor

// Scratch buffers (no cudaMalloc allowed -> device globals)
__device__ float g_q [MTOT * D_MODEL];            // q (fp32, pre-norm)
__device__ float g_z [MTOT * D_MODEL];            // attention output
__device__ __nv_bfloat16 g_ahi[MTOT * D_MODEL];   // A-hi (x, then z)
__device__ __nv_bfloat16 g_alo[MTOT * D_MODEL];   // A-lo
__device__ __nv_bfloat16 g_bhi[3 * D_MODEL * D_MODEL]; // B-hi (Wqkv, then Wo)
__device__ __nv_bfloat16 g_blo[3 * D_MODEL * D_MODEL]; // B-lo
__device__ __nv_bfloat16 g_qhi[MTOT * D_MODEL];   // normalized q, hi/lo
__device__ __nv_bfloat16 g_qlo[MTOT * D_MODEL];
__device__ __nv_bfloat16 g_khi[MTOT * D_MODEL];   // normalized k, hi/lo
__device__ __nv_bfloat16 g_klo[MTOT * D_MODEL];
__device__ __nv_bfloat16 g_vhi[MTOT * D_MODEL];   // v, hi/lo
__device__ __nv_bfloat16 g_vlo[MTOT * D_MODEL];

typedef unsigned long long u64;

// ---------------------------------------------------------------------------
// Base-target tensor-core helpers (sm_80+ ISA: ldmatrix / mma.sync / cp.async)
// ---------------------------------------------------------------------------
__device__ __forceinline__ uint32_t smem_u32(const void* p) {
    uint32_t a;
    asm("{ .reg .u64 t; cvta.to.shared.u64 t, %1; cvt.u32.u64 %0, t; }"
        : "=r"(a) : "l"(p));
    return a;
}
__device__ __forceinline__ void ldsm_x4(uint32_t& r0, uint32_t& r1,
                                        uint32_t& r2, uint32_t& r3, uint32_t addr) {
    asm volatile("ldmatrix.sync.aligned.m8n8.x4.shared.b16 {%0,%1,%2,%3}, [%4];"
                 : "=r"(r0), "=r"(r1), "=r"(r2), "=r"(r3) : "r"(addr));
}
__device__ __forceinline__ void ldsm_x4_t(uint32_t& r0, uint32_t& r1,
                                          uint32_t& r2, uint32_t& r3, uint32_t addr) {
    asm volatile("ldmatrix.sync.aligned.m8n8.x4.trans.shared.b16 {%0,%1,%2,%3}, [%4];"
                 : "=r"(r0), "=r"(r1), "=r"(r2), "=r"(r3) : "r"(addr));
}
__device__ __forceinline__ void mma16816(float* d, const uint32_t* a,
                                         const uint32_t* b) {
    asm volatile("mma.sync.aligned.m16n8k16.row.col.f32.bf16.bf16.f32 "
                 "{%0,%1,%2,%3}, {%4,%5,%6,%7}, {%8,%9}, {%0,%1,%2,%3};"
                 : "+f"(d[0]), "+f"(d[1]), "+f"(d[2]), "+f"(d[3])
                 : "r"(a[0]), "r"(a[1]), "r"(a[2]), "r"(a[3]),
                   "r"(b[0]), "r"(b[1]));
}
__device__ __forceinline__ void cp_async16(uint32_t dst, const void* src) {
    asm volatile("cp.async.cg.shared.global [%0], [%1], 16;"
                 :: "r"(dst), "l"(src) : "memory");
}
__device__ __forceinline__ void cp_commit() {
    asm volatile("cp.async.commit_group;" ::: "memory");
}
template <int N>
__device__ __forceinline__ void cp_wait() {
    asm volatile("cp.async.wait_group %0;" :: "n"(N) : "memory");
}
// pack two fp32 -> bf16x2 (x -> low half, y -> high half), round-to-nearest
__device__ __forceinline__ uint32_t bf2pk(float x, float y) {
    uint32_t r;
    asm("cvt.rn.bf16x2.f32 %0, %1, %2;" : "=r"(r) : "f"(y), "f"(x));
    return r;
}
// split pair (p0,p1) into packed hi bf16x2 and packed lo bf16x2
__device__ __forceinline__ void split_pair(float p0, float p1,
                                           uint32_t& hpk, uint32_t& lpk) {
    hpk = bf2pk(p0, p1);
    float h0 = __uint_as_float(hpk << 16);
    float h1 = __uint_as_float(hpk & 0xffff0000u);
    lpk = bf2pk(p0 - h0, p1 - h1);
}

// ---------------------------------------------------------------------------
// fp32 -> (bf16 hi, bf16 lo) split, vectorized
// ---------------------------------------------------------------------------
__global__ __launch_bounds__(256)
void split_f32(const float* __restrict__ src, __nv_bfloat16* __restrict__ hi,
               __nv_bfloat16* __restrict__ lo, int n)
{
    int i = (blockIdx.x * 256 + threadIdx.x) * 4;
    if (i >= n) return;
    float4 x = *(const float4*)(src + i);
    uint32_t h01, l01, h23, l23;
    split_pair(x.x, x.y, h01, l01);
    split_pair(x.z, x.w, h23, l23);
    uint2 hv = {h01, h23}, lv = {l01, l23};
    *(uint2*)(hi + i) = hv;
    *(uint2*)(lo + i) = lv;
}

// ---------------------------------------------------------------------------
// Fused RMSNorm (128-elem head vectors) + bf16 hi/lo split output
// ---------------------------------------------------------------------------
__global__ __launch_bounds__(256)
void rmsnorm_split(const float* __restrict__ in, __nv_bfloat16* __restrict__ hi,
                   __nv_bfloat16* __restrict__ lo, const float* __restrict__ w)
{
    const int row  = blockIdx.x * 8 + (threadIdx.x >> 5);
    const int lane = threadIdx.x & 31;
    const size_t base = (size_t)row * DHEAD + lane * 4;
    float4 xv = *(const float4*)(in + base);
    float ss = xv.x * xv.x + xv.y * xv.y + xv.z * xv.z + xv.w * xv.w;
#pragma unroll
    for (int msk = 16; msk; msk >>= 1)
        ss += __shfl_xor_sync(0xffffffffu, ss, msk);
    const float r = rsqrtf(ss * (1.0f / 128.0f) + 1e-6f);
    float4 wv = *(const float4*)(w + lane * 4);
    float y0 = xv.x * r * wv.x, y1 = xv.y * r * wv.y;
    float y2 = xv.z * r * wv.z, y3 = xv.w * r * wv.w;
    uint32_t h01, l01, h23, l23;
    split_pair(y0, y1, h01, l01);
    split_pair(y2, y3, h23, l23);
    uint2 hv = {h01, h23}, lv = {l01, l23};
    *(uint2*)(hi + base) = hv;
    *(uint2*)(lo + base) = lv;
}

// ---------------------------------------------------------------------------
// HMMA (mma.sync) GEMM with bf16x3 fp32 emulation (unchanged from R13 pass).
// ---------------------------------------------------------------------------
#define GK    2048
#define BK2   32
#define APAD  40
#define PART_ELE (128 * APAD)
#define STAGE_B  (4 * PART_ELE * 2)
#define GEMM_SMEM (2 * STAGE_B)

__global__ __launch_bounds__(256, 2)
void gemm_mma(const __nv_bfloat16* __restrict__ Ahi, const __nv_bfloat16* __restrict__ Alo,
              const __nv_bfloat16* __restrict__ Bhi, const __nv_bfloat16* __restrict__ Blo,
              const float* __restrict__ bias,
              float* __restrict__ out0, float* __restrict__ out1,
              float* __restrict__ out2, int segN)
{
    extern __shared__ __align__(16) __nv_bfloat16 smem[];
    const uint32_t sb = smem_u32(smem);

    const int tid    = threadIdx.x;
    const int wid    = tid >> 5;
    const int lane   = tid & 31;
    const int warp_m = wid >> 2;
    const int warp_n = wid & 3;
    const int wm0    = warp_m * 64;
    const int wn0    = warp_n * 32;
    const int m0     = blockIdx.y * 128;
    const int n0     = blockIdx.x * 128;

    const __nv_bfloat16* gsrc[4];
    gsrc[0] = Ahi + (size_t)m0 * GK;
    gsrc[1] = Alo + (size_t)m0 * GK;
    gsrc[2] = Bhi + (size_t)n0 * GK;
    gsrc[3] = Blo + (size_t)n0 * GK;

    float acc[4][4][4];
#pragma unroll
    for (int mi = 0; mi < 4; mi++)
#pragma unroll
        for (int ni = 0; ni < 4; ni++)
#pragma unroll
            for (int e = 0; e < 4; e++) acc[mi][ni][e] = 0.f;

    auto load_tile = [&](int t, int buf) {
        const uint32_t sbase = sb + buf * STAGE_B;
#pragma unroll
        for (int p = 0; p < 4; p++) {
            const __nv_bfloat16* s = gsrc[p] + t * BK2;
            const uint32_t dbase = sbase + p * (PART_ELE * 2);
#pragma unroll
            for (int i = 0; i < 2; i++) {
                int idx = tid + i * 256;
                int r   = idx >> 2;
                int c   = (idx & 3) * 8;
                cp_async16(dbase + (r * APAD + c) * 2,
                           s + (size_t)r * GK + c);
            }
        }
        cp_commit();
    };

    load_tile(0, 0);

    const int ntiles = GK / BK2;
    for (int t = 0; t < ntiles; t++) {
        const int buf = t & 1;
        if (t + 1 < ntiles) load_tile(t + 1, buf ^ 1);
        if (t + 1 < ntiles) cp_wait<1>(); else cp_wait<0>();
        __syncthreads();

        const uint32_t aHiB = sb + buf * STAGE_B;
        const uint32_t aLoB = aHiB + PART_ELE * 2;
        const uint32_t bHiB = aHiB + 2 * PART_ELE * 2;
        const uint32_t bLoB = aHiB + 3 * PART_ELE * 2;

#pragma unroll
        for (int ks = 0; ks < 2; ks++) {
            const int brow = wn0 + ((lane >> 4) & 1) * 8 + (lane & 7);
            const int bkof = ks * 16 + ((lane >> 3) & 1) * 8;
            uint32_t bh[2][4], bl[2][4];
#pragma unroll
            for (int ni2 = 0; ni2 < 2; ni2++) {
                const uint32_t boff = ((brow + ni2 * 16) * APAD + bkof) * 2;
                ldsm_x4(bh[ni2][0], bh[ni2][1], bh[ni2][2], bh[ni2][3], bHiB + boff);
                ldsm_x4(bl[ni2][0], bl[ni2][1], bl[ni2][2], bl[ni2][3], bLoB + boff);
            }
            const int arow = wm0 + (lane & 15);
            const int akof = ks * 16 + (lane >> 4) * 8;
#pragma unroll
            for (int mi = 0; mi < 4; mi++) {
                const uint32_t aoff = ((arow + mi * 16) * APAD + akof) * 2;
                uint32_t ah[4], al[4];
                ldsm_x4(ah[0], ah[1], ah[2], ah[3], aHiB + aoff);
                ldsm_x4(al[0], al[1], al[2], al[3], aLoB + aoff);
#pragma unroll
                for (int ni = 0; ni < 4; ni++) {
                    const uint32_t* bhp = &bh[ni >> 1][(ni & 1) * 2];
                    const uint32_t* blp = &bl[ni >> 1][(ni & 1) * 2];
                    mma16816(acc[mi][ni], ah, bhp);
                    mma16816(acc[mi][ni], ah, blp);
                    mma16816(acc[mi][ni], al, bhp);
                }
            }
        }
        __syncthreads();
    }

    const int seg = n0 / segN;
    float* o = (seg == 0) ? out0 : ((seg == 1) ? out1 : out2);
    const int nseg0 = n0 - seg * segN;
#pragma unroll
    for (int mi = 0; mi < 4; mi++) {
        const int gm = m0 + wm0 + mi * 16 + (lane >> 2);
#pragma unroll
        for (int ni = 0; ni < 4; ni++) {
            const int gn  = n0 + wn0 + ni * 8 + (lane & 3) * 2;
            const int cn  = nseg0 + (gn - n0);
            float2 bv = *(const float2*)(bias + gn);
            float2 v0, v1;
            v0.x = acc[mi][ni][0] + bv.x;
            v0.y = acc[mi][ni][1] + bv.y;
            v1.x = acc[mi][ni][2] + bv.x;
            v1.y = acc[mi][ni][3] + bv.y;
            *(float2*)(o + (size_t)gm * segN + cn)       = v0;
            *(float2*)(o + (size_t)(gm + 8) * segN + cn) = v1;
        }
    }
}

// ---------------------------------------------------------------------------
// Tensor-core flash attention (non-causal, scale=1.0), bf16x3 fp32 emulation.
// Grid: (SEQ/128, NHEADS, BATCH). Block 256 = 8 warps, each warp owns 16 q-rows.
// Per key-block (64 keys):
//   S = Q K^T via 3 MMA passes (qhi*khi + qhi*klo + qlo*khi)
//   online softmax in registers; P split to bf16 hi/lo IN REGISTERS
//   (m16n8 accumulator == m16n8k16 A-fragment identity -> no smem round trip)
//   O += P V via 3 MMA passes, V fragments loaded with ldmatrix.trans
// ---------------------------------------------------------------------------
#define AT_PAD 136                          // bf16 row stride (128 + 8)
#define AT_SMEM ((128 * 2 + 64 * 4) * AT_PAD * 2)   // 139264 bytes

__global__ __launch_bounds__(256, 1)
void attn_mma(const __nv_bfloat16* __restrict__ Qh_g, const __nv_bfloat16* __restrict__ Ql_g,
              const __nv_bfloat16* __restrict__ Kh_g, const __nv_bfloat16* __restrict__ Kl_g,
              const __nv_bfloat16* __restrict__ Vh_g, const __nv_bfloat16* __restrict__ Vl_g,
              float* __restrict__ Z)
{
    extern __shared__ __align__(16) __nv_bfloat16 asm_smem[];
    __nv_bfloat16* Qh = asm_smem;
    __nv_bfloat16* Ql = Qh + 128 * AT_PAD;
    __nv_bfloat16* Kh = Ql + 128 * AT_PAD;
    __nv_bfloat16* Kl = Kh + 64 * AT_PAD;
    __nv_bfloat16* Vh = Kl + 64 * AT_PAD;
    __nv_bfloat16* Vl = Vh + 64 * AT_PAD;

    const uint32_t sQh = smem_u32(Qh);
    const uint32_t sQl = smem_u32(Ql);
    const uint32_t sKh = smem_u32(Kh);
    const uint32_t sKl = smem_u32(Kl);
    const uint32_t sVh = smem_u32(Vh);
    const uint32_t sVl = smem_u32(Vl);

    const int tid  = threadIdx.x;
    const int wid  = tid >> 5;
    const int lane = tid & 31;
    const int wm0  = wid * 16;
    const int q0   = blockIdx.x * 128;
    const int h    = blockIdx.y;
    const int b    = blockIdx.z;
    const size_t rowbase = (size_t)b * SEQ;
    const int    hb      = h * DHEAD;

    // Q tile -> smem (hi/lo), reused across all key blocks
#pragma unroll
    for (int i = 0; i < 8; i++) {
        int u = tid + i * 256;              // 0..2047
        int r = u >> 4;
        int c = (u & 15) * 8;
        const size_t g = (rowbase + q0 + r) * D_MODEL + hb + c;
        *(uint4*)(Qh + r * AT_PAD + c) = *(const uint4*)(Qh_g + g);
        *(uint4*)(Ql + r * AT_PAD + c) = *(const uint4*)(Ql_g + g);
    }

    float o[16][4];
#pragma unroll
    for (int ni = 0; ni < 16; ni++)
#pragma unroll
        for (int e = 0; e < 4; e++) o[ni][e] = 0.f;
    float m0 = -1e30f, m1 = -1e30f, l0 = 0.f, l1 = 0.f;

    for (int kb = 0; kb < SEQ / 64; kb++) {
        __syncthreads();                    // previous PV finished reading K/V smem
        const size_t k0g = rowbase + (size_t)kb * 64;
#pragma unroll
        for (int i = 0; i < 4; i++) {
            int u = tid + i * 256;          // 0..1023
            int r = u >> 4;
            int c = (u & 15) * 8;
            const size_t g = (k0g + r) * D_MODEL + hb + c;
            *(uint4*)(Kh + r * AT_PAD + c) = *(const uint4*)(Kh_g + g);
            *(uint4*)(Kl + r * AT_PAD + c) = *(const uint4*)(Kl_g + g);
            *(uint4*)(Vh + r * AT_PAD + c) = *(const uint4*)(Vh_g + g);
            *(uint4*)(Vl + r * AT_PAD + c) = *(const uint4*)(Vl_g + g);
        }
        __syncthreads();

        // ---- S = Q K^T (per warp: 16 x 64), 3-pass emulation ----
        float s[8][4];
#pragma unroll
        for (int j = 0; j < 8; j++)
#pragma unroll
            for (int e = 0; e < 4; e++) s[j][e] = 0.f;

        const uint32_t qoffb = ((wm0 + (lane & 15)) * AT_PAD + (lane >> 4) * 8) * 2;
        const uint32_t krow  = ((lane >> 4) & 1) * 8 + (lane & 7);
        const uint32_t kcolb = ((lane >> 3) & 1) * 8;
#pragma unroll
        for (int ks = 0; ks < 8; ks++) {
            uint32_t ah[4], al[4];
            const uint32_t qoff = qoffb + ks * 32;     // +16 bf16 cols = 32B
            ldsm_x4(ah[0], ah[1], ah[2], ah[3], sQh + qoff);
            ldsm_x4(al[0], al[1], al[2], al[3], sQl + qoff);
#pragma unroll
            for (int np = 0; np < 4; np++) {
                uint32_t bh4[4], bl4[4];
                const uint32_t koff = ((np * 16 + krow) * AT_PAD + ks * 16 + kcolb) * 2;
                ldsm_x4(bh4[0], bh4[1], bh4[2], bh4[3], sKh + koff);
                ldsm_x4(bl4[0], bl4[1], bl4[2], bl4[3], sKl + koff);
                mma16816(s[np * 2],     ah, &bh4[0]);
                mma16816(s[np * 2],     ah, &bl4[0]);
                mma16816(s[np * 2],     al, &bh4[0]);
                mma16816(s[np * 2 + 1], ah, &bh4[2]);
                mma16816(s[np * 2 + 1], ah, &bl4[2]);
                mma16816(s[np * 2 + 1], al, &bh4[2]);
            }
        }

        // ---- online softmax (rows r = lane>>2 and r+8) ----
        float mx0 = -1e30f, mx1 = -1e30f;
#pragma unroll
        for (int j = 0; j < 8; j++) {
            mx0 = fmaxf(mx0, fmaxf(s[j][0], s[j][1]));
            mx1 = fmaxf(mx1, fmaxf(s[j][2], s[j][3]));
        }
        mx0 = fmaxf(mx0, __shfl_xor_sync(0xffffffffu, mx0, 1));
        mx0 = fmaxf(mx0, __shfl_xor_sync(0xffffffffu, mx0, 2));
        mx1 = fmaxf(mx1, __shfl_xor_sync(0xffffffffu, mx1, 1));
        mx1 = fmaxf(mx1, __shfl_xor_sync(0xffffffffu, mx1, 2));
        const float mn0 = fmaxf(m0, mx0);
        const float mn1 = fmaxf(m1, mx1);
        const float c0 = __expf(m0 - mn0);
        const float c1 = __expf(m1 - mn1);
        m0 = mn0; m1 = mn1;
        float rs0 = 0.f, rs1 = 0.f;
#pragma unroll
        for (int j = 0; j < 8; j++) {
            s[j][0] = __expf(s[j][0] - mn0);
            s[j][1] = __expf(s[j][1] - mn0);
            s[j][2] = __expf(s[j][2] - mn1);
            s[j][3] = __expf(s[j][3] - mn1);
            rs0 += s[j][0] + s[j][1];
            rs1 += s[j][2] + s[j][3];
        }
        rs0 += __shfl_xor_sync(0xffffffffu, rs0, 1);
        rs0 += __shfl_xor_sync(0xffffffffu, rs0, 2);
        rs1 += __shfl_xor_sync(0xffffffffu, rs1, 1);
        rs1 += __shfl_xor_sync(0xffffffffu, rs1, 2);
        l0 = l0 * c0 + rs0;
        l1 = l1 * c1 + rs1;
#pragma unroll
        for (int ni = 0; ni < 16; ni++) {
            o[ni][0] *= c0; o[ni][1] *= c0;
            o[ni][2] *= c1; o[ni][3] *= c1;
        }

        // ---- pack P into A-fragments (hi/lo), pure registers ----
        uint32_t ph[4][4], pl[4][4];
#pragma unroll
        for (int t = 0; t < 4; t++) {
            split_pair(s[2 * t][0],     s[2 * t][1],     ph[t][0], pl[t][0]);
            split_pair(s[2 * t][2],     s[2 * t][3],     ph[t][1], pl[t][1]);
            split_pair(s[2 * t + 1][0], s[2 * t + 1][1], ph[t][2], pl[t][2]);
            split_pair(s[2 * t + 1][2], s[2 * t + 1][3], ph[t][3], pl[t][3]);
        }

        // ---- O += P V  (V via ldmatrix.trans; per warp 16 x 128) ----
        const uint32_t vrow  = ((lane >> 3) & 1) * 8 + (lane & 7);
        const uint32_t vcolb = ((lane >> 4) & 1) * 8;
#pragma unroll
        for (int t = 0; t < 4; t++) {
#pragma unroll
            for (int np = 0; np < 8; np++) {
                uint32_t vh4[4], vl4[4];
                const uint32_t voff = ((t * 16 + vrow) * AT_PAD + np * 16 + vcolb) * 2;
                ldsm_x4_t(vh4[0], vh4[1], vh4[2], vh4[3], sVh + voff);
                ldsm_x4_t(vl4[0], vl4[1], vl4[2], vl4[3], sVl + voff);
                mma16816(o[np * 2],     ph[t], &vh4[0]);
                mma16816(o[np * 2],     ph[t], &vl4[0]);
                mma16816(o[np * 2],     pl[t], &vh4[0]);
                mma16816(o[np * 2 + 1], ph[t], &vh4[2]);
                mma16816(o[np * 2 + 1], ph[t], &vl4[2]);
                mma16816(o[np * 2 + 1], pl[t], &vh4[2]);
            }
        }
    }

    // ---- normalize & store Z [b, s, h*dh] ----
    const float inv0 = 1.f / l0, inv1 = 1.f / l1;
    const int r  = lane >> 2;
    const int c2 = (lane & 3) * 2;
    const size_t row0 = rowbase + q0 + wm0 + r;
#pragma unroll
    for (int ni = 0; ni < 16; ni++) {
        const int col = hb + ni * 8 + c2;
        float2 v0, v1;
        v0.x = o[ni][0] * inv0; v0.y = o[ni][1] * inv0;
        v1.x = o[ni][2] * inv1; v1.y = o[ni][3] * inv1;
        *(float2*)(Z + row0 * D_MODEL + col)       = v0;
        *(float2*)(Z + (row0 + 8) * D_MODEL + col) = v1;
    }
}

// ---------------------------------------------------------------------------
// Launch
// ---------------------------------------------------------------------------
extern "C" void kernel_launch(void* const* d_in, const int* in_sizes, int n_in,
                              void* d_out, int out_size)
{
    const float* x    = (const float*)d_in[0];
    const float* Wqkv = (const float*)d_in[1];
    const float* bqkv = (const float*)d_in[2];
    const float* Wo   = (const float*)d_in[3];
    const float* bo   = (const float*)d_in[4];
    const float* wq   = (const float*)d_in[5];
    const float* wk   = (const float*)d_in[6];

    float* out  = (float*)d_out;
    float* kout = out + (size_t)OUTSZ;       // k_new (pre-norm)
    float* vout = out + (size_t)2 * OUTSZ;   // v_new

    float *qbuf, *zbuf;
    __nv_bfloat16 *ahi, *alo, *bhi, *blo, *qhi, *qlo, *khi, *klo, *vhi, *vlo;
    cudaGetSymbolAddress((void**)&qbuf, g_q);
    cudaGetSymbolAddress((void**)&zbuf, g_z);
    cudaGetSymbolAddress((void**)&ahi,  g_ahi);
    cudaGetSymbolAddress((void**)&alo,  g_alo);
    cudaGetSymbolAddress((void**)&bhi,  g_bhi);
    cudaGetSymbolAddress((void**)&blo,  g_blo);
    cudaGetSymbolAddress((void**)&qhi,  g_qhi);
    cudaGetSymbolAddress((void**)&qlo,  g_qlo);
    cudaGetSymbolAddress((void**)&khi,  g_khi);
    cudaGetSymbolAddress((void**)&klo,  g_klo);
    cudaGetSymbolAddress((void**)&vhi,  g_vhi);
    cudaGetSymbolAddress((void**)&vlo,  g_vlo);

    cudaFuncSetAttribute(gemm_mma,
                         cudaFuncAttributeMaxDynamicSharedMemorySize, GEMM_SMEM);
    cudaFuncSetAttribute(attn_mma,
                         cudaFuncAttributeMaxDynamicSharedMemorySize, AT_SMEM);

    // 1) split x and Wqkv into bf16 hi/lo
    split_f32<<<OUTSZ / 1024, 256>>>(x, ahi, alo, OUTSZ);
    split_f32<<<(3 * D_MODEL * D_MODEL) / 1024, 256>>>(Wqkv, bhi, blo,
                                                       3 * D_MODEL * D_MODEL);

    // 2) QKV projection: q -> scratch, k/v -> output regions
    gemm_mma<<<dim3(3 * D_MODEL / 128, MTOT / 128), 256, GEMM_SMEM>>>(
        ahi, alo, bhi, blo, bqkv, qbuf, kout, vout, D_MODEL);

    // 3) fused RMSNorm + bf16 hi/lo split for q and k; plain split for v
    rmsnorm_split<<<(MTOT * NHEADS) / 8, 256>>>(qbuf, qhi, qlo, wq);
    rmsnorm_split<<<(MTOT * NHEADS) / 8, 256>>>(kout, khi, klo, wk);
    split_f32<<<OUTSZ / 1024, 256>>>(vout, vhi, vlo, OUTSZ);

    // 4) tensor-core flash attention -> z scratch
    attn_mma<<<dim3(SEQ / 128, NHEADS, BATCH), 256, AT_SMEM>>>(
        qhi, qlo, khi, klo, vhi, vlo, zbuf);

    // 5) split z and Wo, output projection
    split_f32<<<OUTSZ / 1024, 256>>>(zbuf, ahi, alo, OUTSZ);
    split_f32<<<(D_MODEL * D_MODEL) / 1024, 256>>>(Wo, bhi, blo,
                                                   D_MODEL * D_MODEL);
    gemm_mma<<<dim3(D_MODEL / 128, MTOT / 128), 256, GEMM_SMEM>>>(
        ahi, alo, bhi, blo, bo, out, out, out, D_MODEL);
}